// round 3
// baseline (speedup 1.0000x reference)
#include <cuda_runtime.h>

// Problem constants
#define NQ 4
#define DIM 16
#define T_STEPS 200
#define NROTS 40      // 5*NQ*NL, NL=2
#define QFF_NROTS 20
#define DEG 3
#define PITCH 41      // padded row pitch in shared (coprime with 32 -> conflict-free)
#define THREADS 256

// ---------- 2x2 rotation primitives (h = theta/2 already folded into c,s) ----------
// RX: a0' = c a0 - i s a1 ; a1' = -i s a0 + c a1
__device__ __forceinline__ void rot_rx(float c, float s,
                                       float& r0, float& i0, float& r1, float& i1) {
    float nr0 = fmaf(c, r0,  s * i1);
    float ni0 = fmaf(c, i0, -s * r1);
    float nr1 = fmaf(c, r1,  s * i0);
    float ni1 = fmaf(c, i1, -s * r0);
    r0 = nr0; i0 = ni0; r1 = nr1; i1 = ni1;
}
// RY: a0' = c a0 - s a1 ; a1' = s a0 + c a1 (real matrix)
__device__ __forceinline__ void rot_ry(float c, float s,
                                       float& r0, float& i0, float& r1, float& i1) {
    float nr0 = fmaf(c, r0, -s * r1);
    float ni0 = fmaf(c, i0, -s * i1);
    float nr1 = fmaf(c, r1,  s * r0);
    float ni1 = fmaf(c, i1,  s * i0);
    r0 = nr0; i0 = ni0; r1 = nr1; i1 = ni1;
}
// RZ: a0' = e^{-ih} a0 ; a1' = e^{+ih} a1
__device__ __forceinline__ void rot_rz(float c, float s,
                                       float& r0, float& i0, float& r1, float& i1) {
    float nr0 = fmaf(c, r0,  s * i0);
    float ni0 = fmaf(c, i0, -s * r0);
    float nr1 = fmaf(c, r1, -s * i1);
    float ni1 = fmaf(c, i1,  s * r1);
    r0 = nr0; i0 = ni0; r1 = nr1; i1 = ni1;
}

// ---------- full-register 16-dim state gates (qubit w has bit-weight W = 8>>w) ----------
template<int W>
__device__ __forceinline__ void g_rx(float c, float s, float* sr, float* si) {
#pragma unroll
    for (int i = 0; i < DIM; i++)
        if (!(i & W)) rot_rx(c, s, sr[i], si[i], sr[i | W], si[i | W]);
}
template<int W>
__device__ __forceinline__ void g_ry(float c, float s, float* sr, float* si) {
#pragma unroll
    for (int i = 0; i < DIM; i++)
        if (!(i & W)) rot_ry(c, s, sr[i], si[i], sr[i | W], si[i | W]);
}
template<int W>
__device__ __forceinline__ void g_rz(float c, float s, float* sr, float* si) {
#pragma unroll
    for (int i = 0; i < DIM; i++)
        if (!(i & W)) rot_rz(c, s, sr[i], si[i], sr[i | W], si[i | W]);
}
template<int CW, int TW>
__device__ __forceinline__ void g_crx(float c, float s, float* sr, float* si) {
#pragma unroll
    for (int i = 0; i < DIM; i++)
        if ((i & CW) && !(i & TW)) rot_rx(c, s, sr[i], si[i], sr[i | TW], si[i | TW]);
}

// One ansatz layer: 20 params. Qubit i: RX,RY,RZ (p[3i..3i+2]); then CRX ring
// forward (c=i, t=i+1 mod 4) p[12..15]; then CRX ring backward (c=i, t=i-1 mod 4)
// with i = 3..0 -> p[16..19]. Angles are p*0.5 (matches _ansatz's half = params*0.5).
__device__ __forceinline__ void ansatz_layer(const float* p, float* sr, float* si) {
    float c, s;
    __sincosf(0.5f * p[0],  &s, &c); g_rx<8>(c, s, sr, si);
    __sincosf(0.5f * p[1],  &s, &c); g_ry<8>(c, s, sr, si);
    __sincosf(0.5f * p[2],  &s, &c); g_rz<8>(c, s, sr, si);
    __sincosf(0.5f * p[3],  &s, &c); g_rx<4>(c, s, sr, si);
    __sincosf(0.5f * p[4],  &s, &c); g_ry<4>(c, s, sr, si);
    __sincosf(0.5f * p[5],  &s, &c); g_rz<4>(c, s, sr, si);
    __sincosf(0.5f * p[6],  &s, &c); g_rx<2>(c, s, sr, si);
    __sincosf(0.5f * p[7],  &s, &c); g_ry<2>(c, s, sr, si);
    __sincosf(0.5f * p[8],  &s, &c); g_rz<2>(c, s, sr, si);
    __sincosf(0.5f * p[9],  &s, &c); g_rx<1>(c, s, sr, si);
    __sincosf(0.5f * p[10], &s, &c); g_ry<1>(c, s, sr, si);
    __sincosf(0.5f * p[11], &s, &c); g_rz<1>(c, s, sr, si);
    __sincosf(0.5f * p[12], &s, &c); g_crx<8, 4>(c, s, sr, si);
    __sincosf(0.5f * p[13], &s, &c); g_crx<4, 2>(c, s, sr, si);
    __sincosf(0.5f * p[14], &s, &c); g_crx<2, 1>(c, s, sr, si);
    __sincosf(0.5f * p[15], &s, &c); g_crx<1, 8>(c, s, sr, si);
    __sincosf(0.5f * p[16], &s, &c); g_crx<1, 2>(c, s, sr, si);
    __sincosf(0.5f * p[17], &s, &c); g_crx<2, 4>(c, s, sr, si);
    __sincosf(0.5f * p[18], &s, &c); g_crx<4, 8>(c, s, sr, si);
    __sincosf(0.5f * p[19], &s, &c); g_crx<8, 1>(c, s, sr, si);
}

__global__ __launch_bounds__(THREADS)
void qac_kernel(const float* __restrict__ tsp,      // (B, T, 40)
                const float* __restrict__ poly,     // (4,)
                const float* __restrict__ mix_re,   // (200,)
                const float* __restrict__ mix_im,   // (200,)
                const float* __restrict__ qff,      // (20,)
                float* __restrict__ out)            // (B, 12)
{
    __shared__ float sp[T_STEPS * PITCH];    // padded params, row t at t*41
    __shared__ float smr[T_STEPS], smi[T_STEPS];
    __shared__ float wv[32];                 // work vector: [0..15]=re, [16..31]=im
    __shared__ float accv[32];               // QSVT accumulator
    __shared__ float part[THREADS / 32][32]; // per-warp partial sums

    const int b    = blockIdx.x;
    const int tid  = threadIdx.x;
    const int lane = tid & 31;
    const int warp = tid >> 5;

    // Stage this batch's params (32KB) into shared — read HBM exactly once.
    const float* gp = tsp + (size_t)b * (T_STEPS * NROTS);
    for (int i = tid; i < T_STEPS * NROTS; i += THREADS) {
        int t = i / NROTS;
        int j = i - t * NROTS;
        sp[t * PITCH + j] = gp[i];
    }
    if (tid < T_STEPS) { smr[tid] = mix_re[tid]; smi[tid] = mix_im[tid]; }
    if (tid < 32) {
        wv[tid]   = (tid == 0) ? 1.0f : 0.0f;           // |0...0>
        accv[tid] = (tid == 0) ? poly[0] : 0.0f;        // c0 * base
    }
    __syncthreads();

    // QSVT iterations: work_k = sum_t coeff[t] * U_{b,t} work_{k-1}
#pragma unroll 1
    for (int k = 1; k <= DEG; k++) {
        float a[32];
        if (tid < T_STEPS) {
            float sr[16], si[16];
#pragma unroll
            for (int q = 0; q < 16; q++) { sr[q] = wv[q]; si[q] = wv[16 + q]; }
            const float* p = sp + tid * PITCH;
#pragma unroll 1
            for (int l = 0; l < 2; l++)
                ansatz_layer(p + 20 * l, sr, si);
            const float cr = smr[tid], ci = smi[tid];
#pragma unroll
            for (int q = 0; q < 16; q++) {
                a[q]      = cr * sr[q] - ci * si[q];
                a[16 + q] = fmaf(cr, si[q], ci * sr[q]);
            }
        } else {
#pragma unroll
            for (int q = 0; q < 32; q++) a[q] = 0.0f;
        }

        // Payload-splitting warp reduction: 31 SHFL total.
        // After it, lane l holds sum over its warp of component l.
#pragma unroll
        for (int m = 16; m >= 1; m >>= 1) {
            const bool hi = (lane & m) != 0;
#pragma unroll
            for (int s = 0; s < m; s++) {
                float snd = hi ? a[s] : a[s + m];
                float kep = hi ? a[s + m] : a[s];
                a[s] = kep + __shfl_xor_sync(0xffffffffu, snd, m);
            }
        }
        part[warp][lane] = a[0];
        __syncthreads();
        if (tid < 32) {
            float sum = 0.0f;
#pragma unroll
            for (int w = 0; w < THREADS / 32; w++) sum += part[w][tid];
            wv[tid] = sum;
            accv[tid] = fmaf(poly[k], sum, accv[tid]);
        }
        __syncthreads();
    }

    // Epilogue: normalize, QFF ansatz, expectation values. One thread per batch.
    if (tid == 0) {
        float l1 = fabsf(poly[0]) + fabsf(poly[1]) + fabsf(poly[2]) + fabsf(poly[3]);
        float inv_l1 = 1.0f / l1;
        float sr[16], si[16];
        float n2 = 0.0f;
#pragma unroll
        for (int q = 0; q < 16; q++) {
            sr[q] = accv[q] * inv_l1;
            si[q] = accv[16 + q] * inv_l1;
            n2 = fmaf(sr[q], sr[q], fmaf(si[q], si[q], n2));
        }
        float inv_n = 1.0f / (sqrtf(n2) + 1e-9f);
#pragma unroll
        for (int q = 0; q < 16; q++) { sr[q] *= inv_n; si[q] *= inv_n; }

        float qp[QFF_NROTS];
#pragma unroll
        for (int j = 0; j < QFF_NROTS; j++) qp[j] = qff[j];
        ansatz_layer(qp, sr, si);

        float* o = out + b * 12;
#pragma unroll
        for (int qi = 0; qi < NQ; qi++) {
            const int W = 8 >> qi;
            float X = 0.0f, Y = 0.0f, Z = 0.0f;
#pragma unroll
            for (int i0 = 0; i0 < DIM; i0++) {
                if (!(i0 & W)) {
                    int j0 = i0 | W;
                    X += 2.0f * (sr[i0] * sr[j0] + si[i0] * si[j0]);
                    Y += 2.0f * (sr[i0] * si[j0] - si[i0] * sr[j0]);
                    Z += (sr[i0] * sr[i0] + si[i0] * si[i0])
                       - (sr[j0] * sr[j0] + si[j0] * si[j0]);
                }
            }
            o[qi] = X; o[4 + qi] = Y; o[8 + qi] = Z;
        }
    }
}

extern "C" void kernel_launch(void* const* d_in, const int* in_sizes, int n_in,
                              void* d_out, int out_size) {
    const float* tsp    = (const float*)d_in[0];
    const float* poly   = (const float*)d_in[1];
    const float* mix_re = (const float*)d_in[2];
    const float* mix_im = (const float*)d_in[3];
    const float* qff    = (const float*)d_in[4];
    float* out = (float*)d_out;
    int B = in_sizes[0] / (T_STEPS * NROTS);   // 2048
    qac_kernel<<<B, THREADS>>>(tsp, poly, mix_re, mix_im, qff, out);
}

// round 4
// speedup vs baseline: 1.0837x; 1.0837x over previous
#include <cuda_runtime.h>

// Problem constants
#define NQ 4
#define DIM 16
#define T_STEPS 200
#define NROTS 40      // 5*NQ*NL, NL=2
#define QFF_NROTS 20
#define DEG 3
#define THREADS 256
#define NSLOT 66      // 64 gate-table slots + 2 coeff slots per timestep

// Dynamic shared layout (floats):
//   tab  [NSLOT * T_STEPS]   transposed gate table: tab[slot*200 + t]
//   wv   [32]                work vector (re[16], im[16])
//   accv [32]                QSVT accumulator
//   part [8*32]              per-warp reduction partials
#define SMEM_FLOATS (NSLOT * T_STEPS + 32 + 32 + 8 * 32)

// ---------- 2x2 rotation primitives (half-angle folded into c,s) ----------
__device__ __forceinline__ void rot_rx(float c, float s,
                                       float& r0, float& i0, float& r1, float& i1) {
    float nr0 = fmaf(c, r0,  s * i1);
    float ni0 = fmaf(c, i0, -s * r1);
    float nr1 = fmaf(c, r1,  s * i0);
    float ni1 = fmaf(c, i1, -s * r0);
    r0 = nr0; i0 = ni0; r1 = nr1; i1 = ni1;
}
__device__ __forceinline__ void rot_ry(float c, float s,
                                       float& r0, float& i0, float& r1, float& i1) {
    float nr0 = fmaf(c, r0, -s * r1);
    float ni0 = fmaf(c, i0, -s * i1);
    float nr1 = fmaf(c, r1,  s * r0);
    float ni1 = fmaf(c, i1,  s * i0);
    r0 = nr0; i0 = ni0; r1 = nr1; i1 = ni1;
}
__device__ __forceinline__ void rot_rz(float c, float s,
                                       float& r0, float& i0, float& r1, float& i1) {
    float nr0 = fmaf(c, r0,  s * i0);
    float ni0 = fmaf(c, i0, -s * r0);
    float nr1 = fmaf(c, r1, -s * i1);
    float ni1 = fmaf(c, i1,  s * r1);
    r0 = nr0; i0 = ni0; r1 = nr1; i1 = ni1;
}

// ---------- 16-dim state gates (qubit w has bit-weight W = 8>>w) ----------
template<int W>
__device__ __forceinline__ void g_rx(float c, float s, float* sr, float* si) {
#pragma unroll
    for (int i = 0; i < DIM; i++)
        if (!(i & W)) rot_rx(c, s, sr[i], si[i], sr[i | W], si[i | W]);
}
template<int W>
__device__ __forceinline__ void g_ry(float c, float s, float* sr, float* si) {
#pragma unroll
    for (int i = 0; i < DIM; i++)
        if (!(i & W)) rot_ry(c, s, sr[i], si[i], sr[i | W], si[i | W]);
}
template<int W>
__device__ __forceinline__ void g_rz(float c, float s, float* sr, float* si) {
#pragma unroll
    for (int i = 0; i < DIM; i++)
        if (!(i & W)) rot_rz(c, s, sr[i], si[i], sr[i | W], si[i | W]);
}
template<int CW, int TW>
__device__ __forceinline__ void g_crx(float c, float s, float* sr, float* si) {
#pragma unroll
    for (int i = 0; i < DIM; i++)
        if ((i & CW) && !(i & TW)) rot_rx(c, s, sr[i], si[i], sr[i | TW], si[i | TW]);
}

// Fused SU(2) gate: U = [[u00, u01], [-conj(u01), conj(u00)]] on qubit weight W.
template<int W>
__device__ __forceinline__ void g_su2(float u00r, float u00i, float u01r, float u01i,
                                      float* sr, float* si) {
#pragma unroll
    for (int i = 0; i < DIM; i++) {
        if (!(i & W)) {
            const int j = i | W;
            float r0 = sr[i], i0 = si[i], r1 = sr[j], i1 = si[j];
            float nr0 = fmaf(u00r, r0, fmaf(-u00i, i0, fmaf(u01r, r1, -u01i * i1)));
            float ni0 = fmaf(u00r, i0, fmaf( u00i, r0, fmaf(u01r, i1,  u01i * r1)));
            float nr1 = fmaf(u00r, r1, fmaf( u00i, i1, fmaf(-u01r, r0, -u01i * i0)));
            float ni1 = fmaf(u00r, i1, fmaf(-u00i, r1, fmaf(-u01r, i0,  u01i * r0)));
            sr[i] = nr0; si[i] = ni0; sr[j] = nr1; si[j] = ni1;
        }
    }
}

// Reference ansatz layer via per-gate rotations (used only in the tiny epilogue).
__device__ __forceinline__ void ansatz_layer_ref(const float* p, float* sr, float* si) {
    float c, s;
    __sincosf(0.5f * p[0],  &s, &c); g_rx<8>(c, s, sr, si);
    __sincosf(0.5f * p[1],  &s, &c); g_ry<8>(c, s, sr, si);
    __sincosf(0.5f * p[2],  &s, &c); g_rz<8>(c, s, sr, si);
    __sincosf(0.5f * p[3],  &s, &c); g_rx<4>(c, s, sr, si);
    __sincosf(0.5f * p[4],  &s, &c); g_ry<4>(c, s, sr, si);
    __sincosf(0.5f * p[5],  &s, &c); g_rz<4>(c, s, sr, si);
    __sincosf(0.5f * p[6],  &s, &c); g_rx<2>(c, s, sr, si);
    __sincosf(0.5f * p[7],  &s, &c); g_ry<2>(c, s, sr, si);
    __sincosf(0.5f * p[8],  &s, &c); g_rz<2>(c, s, sr, si);
    __sincosf(0.5f * p[9],  &s, &c); g_rx<1>(c, s, sr, si);
    __sincosf(0.5f * p[10], &s, &c); g_ry<1>(c, s, sr, si);
    __sincosf(0.5f * p[11], &s, &c); g_rz<1>(c, s, sr, si);
    __sincosf(0.5f * p[12], &s, &c); g_crx<8, 4>(c, s, sr, si);
    __sincosf(0.5f * p[13], &s, &c); g_crx<4, 2>(c, s, sr, si);
    __sincosf(0.5f * p[14], &s, &c); g_crx<2, 1>(c, s, sr, si);
    __sincosf(0.5f * p[15], &s, &c); g_crx<1, 8>(c, s, sr, si);
    __sincosf(0.5f * p[16], &s, &c); g_crx<1, 2>(c, s, sr, si);
    __sincosf(0.5f * p[17], &s, &c); g_crx<2, 4>(c, s, sr, si);
    __sincosf(0.5f * p[18], &s, &c); g_crx<4, 8>(c, s, sr, si);
    __sincosf(0.5f * p[19], &s, &c); g_crx<8, 1>(c, s, sr, si);
}

__global__ __launch_bounds__(THREADS)
void qac_kernel(const float* __restrict__ tsp,      // (B, T, 40)
                const float* __restrict__ poly,     // (4,)
                const float* __restrict__ mix_re,   // (200,)
                const float* __restrict__ mix_im,   // (200,)
                const float* __restrict__ qff,      // (20,)
                float* __restrict__ out)            // (B, 12)
{
    extern __shared__ float sm[];
    float* tab  = sm;                       // [NSLOT][T_STEPS], transposed
    float* wv   = sm + NSLOT * T_STEPS;     // 32
    float* accv = wv + 32;                  // 32
    float* part = accv + 32;                // 8*32

    const int b    = blockIdx.x;
    const int tid  = threadIdx.x;
    const int lane = tid & 31;
    const int warp = tid >> 5;

    // ---- Precompute phase: build per-timestep gate table (once, reused for 3 k) ----
    if (tid < T_STEPS) {
        // Load this timestep's 40 params (160B aligned -> float4)
        const float4* p4 = (const float4*)(tsp + (size_t)b * (T_STEPS * NROTS) + tid * NROTS);
        float pr[NROTS];
#pragma unroll
        for (int j = 0; j < NROTS / 4; j++) {
            float4 v = p4[j];
            pr[4 * j] = v.x; pr[4 * j + 1] = v.y; pr[4 * j + 2] = v.z; pr[4 * j + 3] = v.w;
        }
        float* col = tab + tid;
#pragma unroll
        for (int l = 0; l < 2; l++) {
            const int base = l * 32;
#pragma unroll
            for (int q = 0; q < 4; q++) {
                float ca, sa, cb, sb, cg, sg;
                __sincosf(0.5f * pr[20 * l + 3 * q],     &sa, &ca);
                __sincosf(0.5f * pr[20 * l + 3 * q + 1], &sb, &cb);
                __sincosf(0.5f * pr[20 * l + 3 * q + 2], &sg, &cg);
                // U = Rz(g)*Ry(b)*Rx(a); store u00, u01 only
                float cbca = cb * ca, cbsa = cb * sa, sbca = sb * ca, sbsa = sb * sa;
                float u00r = fmaf(cg, cbca,  sg * sbsa);
                float u00i = fmaf(cg, sbsa, -sg * cbca);
                float u01r = -fmaf(cg, sbca,  sg * cbsa);
                float u01i = fmaf(sg, sbca, -cg * cbsa);
                col[(base + 4 * q    ) * T_STEPS] = u00r;
                col[(base + 4 * q + 1) * T_STEPS] = u00i;
                col[(base + 4 * q + 2) * T_STEPS] = u01r;
                col[(base + 4 * q + 3) * T_STEPS] = u01i;
            }
#pragma unroll
            for (int g = 0; g < 8; g++) {
                float c, s;
                __sincosf(0.5f * pr[20 * l + 12 + g], &s, &c);
                col[(base + 16 + 2 * g    ) * T_STEPS] = c;
                col[(base + 16 + 2 * g + 1) * T_STEPS] = s;
            }
        }
        col[64 * T_STEPS] = mix_re[tid];
        col[65 * T_STEPS] = mix_im[tid];
    }
    if (tid < 32) {
        wv[tid]   = (tid == 0) ? 1.0f : 0.0f;        // |0...0>
        accv[tid] = (tid == 0) ? poly[0] : 0.0f;     // c0 * base
    }
    __syncthreads();

    const float* col = tab + tid;    // this thread's timestep column (tid < 200)
    float cr = 0.0f, ci = 0.0f;
    if (tid < T_STEPS) { cr = col[64 * T_STEPS]; ci = col[65 * T_STEPS]; }

    // ---- QSVT iterations: work_k = sum_t coeff[t] * U_{b,t} work_{k-1} ----
#pragma unroll 1
    for (int k = 1; k <= DEG; k++) {
        float a[32];
        if (tid < T_STEPS) {
            float sr[16], si[16];
#pragma unroll
            for (int q = 0; q < 16; q++) { sr[q] = wv[q]; si[q] = wv[16 + q]; }
#pragma unroll
            for (int l = 0; l < 2; l++) {
                const int base = l * 32;
                // fused single-qubit gates, qubit 0..3 (weights 8,4,2,1)
                g_su2<8>(col[(base + 0)  * T_STEPS], col[(base + 1)  * T_STEPS],
                         col[(base + 2)  * T_STEPS], col[(base + 3)  * T_STEPS], sr, si);
                g_su2<4>(col[(base + 4)  * T_STEPS], col[(base + 5)  * T_STEPS],
                         col[(base + 6)  * T_STEPS], col[(base + 7)  * T_STEPS], sr, si);
                g_su2<2>(col[(base + 8)  * T_STEPS], col[(base + 9)  * T_STEPS],
                         col[(base + 10) * T_STEPS], col[(base + 11) * T_STEPS], sr, si);
                g_su2<1>(col[(base + 12) * T_STEPS], col[(base + 13) * T_STEPS],
                         col[(base + 14) * T_STEPS], col[(base + 15) * T_STEPS], sr, si);
                // CRX ring forward then backward
                g_crx<8, 4>(col[(base + 16) * T_STEPS], col[(base + 17) * T_STEPS], sr, si);
                g_crx<4, 2>(col[(base + 18) * T_STEPS], col[(base + 19) * T_STEPS], sr, si);
                g_crx<2, 1>(col[(base + 20) * T_STEPS], col[(base + 21) * T_STEPS], sr, si);
                g_crx<1, 8>(col[(base + 22) * T_STEPS], col[(base + 23) * T_STEPS], sr, si);
                g_crx<1, 2>(col[(base + 24) * T_STEPS], col[(base + 25) * T_STEPS], sr, si);
                g_crx<2, 4>(col[(base + 26) * T_STEPS], col[(base + 27) * T_STEPS], sr, si);
                g_crx<4, 8>(col[(base + 28) * T_STEPS], col[(base + 29) * T_STEPS], sr, si);
                g_crx<8, 1>(col[(base + 30) * T_STEPS], col[(base + 31) * T_STEPS], sr, si);
            }
#pragma unroll
            for (int q = 0; q < 16; q++) {
                a[q]      = cr * sr[q] - ci * si[q];
                a[16 + q] = fmaf(cr, si[q], ci * sr[q]);
            }
        } else {
#pragma unroll
            for (int q = 0; q < 32; q++) a[q] = 0.0f;
        }

        // Payload-splitting warp reduction: 31 SHFL total.
#pragma unroll
        for (int m = 16; m >= 1; m >>= 1) {
            const bool hi = (lane & m) != 0;
#pragma unroll
            for (int s = 0; s < m; s++) {
                float snd = hi ? a[s] : a[s + m];
                float kep = hi ? a[s + m] : a[s];
                a[s] = kep + __shfl_xor_sync(0xffffffffu, snd, m);
            }
        }
        part[warp * 32 + lane] = a[0];
        __syncthreads();
        if (tid < 32) {
            float sum = 0.0f;
#pragma unroll
            for (int w = 0; w < THREADS / 32; w++) sum += part[w * 32 + tid];
            wv[tid] = sum;
            accv[tid] = fmaf(poly[k], sum, accv[tid]);
        }
        __syncthreads();
    }

    // ---- Epilogue: normalize, QFF ansatz, expectation values ----
    if (tid == 0) {
        float l1 = fabsf(poly[0]) + fabsf(poly[1]) + fabsf(poly[2]) + fabsf(poly[3]);
        float inv_l1 = 1.0f / l1;
        float sr[16], si[16];
        float n2 = 0.0f;
#pragma unroll
        for (int q = 0; q < 16; q++) {
            sr[q] = accv[q] * inv_l1;
            si[q] = accv[16 + q] * inv_l1;
            n2 = fmaf(sr[q], sr[q], fmaf(si[q], si[q], n2));
        }
        float inv_n = 1.0f / (sqrtf(n2) + 1e-9f);
#pragma unroll
        for (int q = 0; q < 16; q++) { sr[q] *= inv_n; si[q] *= inv_n; }

        float qp[QFF_NROTS];
#pragma unroll
        for (int j = 0; j < QFF_NROTS; j++) qp[j] = qff[j];
        ansatz_layer_ref(qp, sr, si);

        float* o = out + b * 12;
#pragma unroll
        for (int qi = 0; qi < NQ; qi++) {
            const int W = 8 >> qi;
            float X = 0.0f, Y = 0.0f, Z = 0.0f;
#pragma unroll
            for (int i0 = 0; i0 < DIM; i0++) {
                if (!(i0 & W)) {
                    int j0 = i0 | W;
                    X += 2.0f * (sr[i0] * sr[j0] + si[i0] * si[j0]);
                    Y += 2.0f * (sr[i0] * si[j0] - si[i0] * sr[j0]);
                    Z += (sr[i0] * sr[i0] + si[i0] * si[i0])
                       - (sr[j0] * sr[j0] + si[j0] * si[j0]);
                }
            }
            o[qi] = X; o[4 + qi] = Y; o[8 + qi] = Z;
        }
    }
}

extern "C" void kernel_launch(void* const* d_in, const int* in_sizes, int n_in,
                              void* d_out, int out_size) {
    const float* tsp    = (const float*)d_in[0];
    const float* poly   = (const float*)d_in[1];
    const float* mix_re = (const float*)d_in[2];
    const float* mix_im = (const float*)d_in[3];
    const float* qff    = (const float*)d_in[4];
    float* out = (float*)d_out;
    int B = in_sizes[0] / (T_STEPS * NROTS);   // 2048

    const int smem_bytes = SMEM_FLOATS * sizeof(float);   // ~54KB
    cudaFuncSetAttribute(qac_kernel, cudaFuncAttributeMaxDynamicSharedMemorySize, smem_bytes);
    qac_kernel<<<B, THREADS, smem_bytes>>>(tsp, poly, mix_re, mix_im, qff, out);
}

// round 5
// speedup vs baseline: 1.2480x; 1.1516x over previous
#include <cuda_runtime.h>

// Problem constants
#define NQ 4
#define DIM 16
#define T_STEPS 200
#define NROTS 40      // 5*NQ*NL, NL=2
#define QFF_NROTS 20
#define DEG 3
#define THREADS 256
#define NSLOT 66      // 64 gate-table slots + 2 coeff slots per timestep

#define SMEM_FLOATS (NSLOT * T_STEPS + 32 + 32 + 8 * 32)

typedef unsigned long long u64;

// ---------- packed f32x2 primitives ----------
__device__ __forceinline__ u64 pk2(float lo, float hi) {
    u64 r; asm("mov.b64 %0, {%1, %2};" : "=l"(r) : "f"(lo), "f"(hi)); return r;
}
__device__ __forceinline__ void upk2(u64 v, float& lo, float& hi) {
    asm("mov.b64 {%0, %1}, %2;" : "=f"(lo), "=f"(hi) : "l"(v));
}
__device__ __forceinline__ u64 swap2(u64 v) {
    float lo, hi; upk2(v, lo, hi); return pk2(hi, lo);
}
__device__ __forceinline__ u64 fma2(u64 a, u64 b, u64 c) {
    u64 d; asm("fma.rn.f32x2 %0, %1, %2, %3;" : "=l"(d) : "l"(a), "l"(b), "l"(c)); return d;
}
__device__ __forceinline__ u64 mul2(u64 a, u64 b) {
    u64 d; asm("mul.rn.f32x2 %0, %1, %2;" : "=l"(d) : "l"(a), "l"(b)); return d;
}

// ---------- packed gates on state vr[8], vi[8] (pack j = amplitudes 2j, 2j+1) ----------

// Fused SU(2), qubit weight W = 2*PW (PW in {4,2,1}).
template<int PW>
__device__ __forceinline__ void su2_pk(float u00r, float u00i, float u01r, float u01i,
                                       u64* vr, u64* vi) {
    u64 A   = pk2(u00r, u00r),  Ai  = pk2(u00i, u00i),  nAi = pk2(-u00i, -u00i);
    u64 B   = pk2(u01r, u01r),  nB  = pk2(-u01r, -u01r);
    u64 Bi  = pk2(u01i, u01i),  nBi = pk2(-u01i, -u01i);
#pragma unroll
    for (int j = 0; j < 8; j++) {
        if (!(j & PW)) {
            const int q = j | PW;
            u64 r0 = vr[j], i0 = vi[j], r1 = vr[q], i1 = vi[q];
            vr[j] = fma2(A, r0, fma2(nAi, i0, fma2(B,  r1, mul2(nBi, i1))));
            vi[j] = fma2(A, i0, fma2(Ai,  r0, fma2(B,  i1, mul2(Bi,  r1))));
            vr[q] = fma2(A, r1, fma2(Ai,  i1, fma2(nB, r0, mul2(nBi, i0))));
            vi[q] = fma2(A, i1, fma2(nAi, r1, fma2(nB, i0, mul2(Bi,  r0))));
        }
    }
}

// Fused SU(2), qubit weight W = 1 (partner inside pack; swapped-operand form).
__device__ __forceinline__ void su2_w1(float u00r, float u00i, float u01r, float u01i,
                                       u64* vr, u64* vi) {
    u64 P  = pk2(u00r,  u00r);
    u64 Q  = pk2(u01r, -u01r);
    u64 R  = pk2(-u00i, u00i);
    u64 S  = pk2(-u01i, -u01i);
    u64 R2 = pk2(u00i, -u00i);
    u64 S2 = pk2(u01i,  u01i);
#pragma unroll
    for (int j = 0; j < 8; j++) {
        u64 rp = vr[j], ip = vi[j];
        u64 rs = swap2(rp), is = swap2(ip);
        vr[j] = fma2(P, rp, fma2(Q, rs, fma2(R,  ip, mul2(S,  is))));
        vi[j] = fma2(P, ip, fma2(Q, is, fma2(R2, rp, mul2(S2, rs))));
    }
}

// CRX with control weight CW=2*PCW (>=2), target weight TW=2*PPW (>=2).
template<int PCW, int PPW>
__device__ __forceinline__ void crx_pk(float c, float s, u64* vr, u64* vi) {
    u64 C = pk2(c, c), Sp = pk2(s, s), nS = pk2(-s, -s);
#pragma unroll
    for (int j = 0; j < 8; j++) {
        if ((j & PCW) && !(j & PPW)) {
            const int q = j | PPW;
            u64 r0 = vr[j], i0 = vi[j], r1 = vr[q], i1 = vi[q];
            vr[j] = fma2(C, r0, mul2(Sp, i1));
            vi[j] = fma2(C, i0, mul2(nS, r1));
            vr[q] = fma2(C, r1, mul2(Sp, i0));
            vi[q] = fma2(C, i1, mul2(nS, r0));
        }
    }
}

// CRX with control weight 1 (control bit = half index): masked coeffs, lo half identity.
template<int PPW>
__device__ __forceinline__ void crx_cw1(float c, float s, u64* vr, u64* vi) {
    u64 C = pk2(1.0f, c), Sp = pk2(0.0f, s), nS = pk2(0.0f, -s);
#pragma unroll
    for (int j = 0; j < 8; j++) {
        if (!(j & PPW)) {
            const int q = j | PPW;
            u64 r0 = vr[j], i0 = vi[j], r1 = vr[q], i1 = vi[q];
            vr[j] = fma2(C, r0, mul2(Sp, i1));
            vi[j] = fma2(C, i0, mul2(nS, r1));
            vr[q] = fma2(C, r1, mul2(Sp, i0));
            vi[q] = fma2(C, i1, mul2(nS, r0));
        }
    }
}

// CRX with target weight 1 (pair inside pack), control weight CW=2*PCW.
template<int PCW>
__device__ __forceinline__ void crx_tw1(float c, float s, u64* vr, u64* vi) {
    u64 C = pk2(c, c), Sp = pk2(s, s), nS = pk2(-s, -s);
#pragma unroll
    for (int j = 0; j < 8; j++) {
        if (j & PCW) {
            u64 rs = swap2(vr[j]), is = swap2(vi[j]);
            vr[j] = fma2(C, vr[j], mul2(Sp, is));
            vi[j] = fma2(C, vi[j], mul2(nS, rs));
        }
    }
}

// ---------- scalar rotations (epilogue only) ----------
__device__ __forceinline__ void rot_rx(float c, float s,
                                       float& r0, float& i0, float& r1, float& i1) {
    float nr0 = fmaf(c, r0,  s * i1);
    float ni0 = fmaf(c, i0, -s * r1);
    float nr1 = fmaf(c, r1,  s * i0);
    float ni1 = fmaf(c, i1, -s * r0);
    r0 = nr0; i0 = ni0; r1 = nr1; i1 = ni1;
}
__device__ __forceinline__ void rot_ry(float c, float s,
                                       float& r0, float& i0, float& r1, float& i1) {
    float nr0 = fmaf(c, r0, -s * r1);
    float ni0 = fmaf(c, i0, -s * i1);
    float nr1 = fmaf(c, r1,  s * r0);
    float ni1 = fmaf(c, i1,  s * i0);
    r0 = nr0; i0 = ni0; r1 = nr1; i1 = ni1;
}
__device__ __forceinline__ void rot_rz(float c, float s,
                                       float& r0, float& i0, float& r1, float& i1) {
    float nr0 = fmaf(c, r0,  s * i0);
    float ni0 = fmaf(c, i0, -s * r0);
    float nr1 = fmaf(c, r1, -s * i1);
    float ni1 = fmaf(c, i1,  s * r1);
    r0 = nr0; i0 = ni0; r1 = nr1; i1 = ni1;
}
template<int W>
__device__ __forceinline__ void g_rx(float c, float s, float* sr, float* si) {
#pragma unroll
    for (int i = 0; i < DIM; i++)
        if (!(i & W)) rot_rx(c, s, sr[i], si[i], sr[i | W], si[i | W]);
}
template<int W>
__device__ __forceinline__ void g_ry(float c, float s, float* sr, float* si) {
#pragma unroll
    for (int i = 0; i < DIM; i++)
        if (!(i & W)) rot_ry(c, s, sr[i], si[i], sr[i | W], si[i | W]);
}
template<int W>
__device__ __forceinline__ void g_rz(float c, float s, float* sr, float* si) {
#pragma unroll
    for (int i = 0; i < DIM; i++)
        if (!(i & W)) rot_rz(c, s, sr[i], si[i], sr[i | W], si[i | W]);
}
template<int CW, int TW>
__device__ __forceinline__ void g_crx(float c, float s, float* sr, float* si) {
#pragma unroll
    for (int i = 0; i < DIM; i++)
        if ((i & CW) && !(i & TW)) rot_rx(c, s, sr[i], si[i], sr[i | TW], si[i | TW]);
}
__device__ __forceinline__ void ansatz_layer_ref(const float* p, float* sr, float* si) {
    float c, s;
    __sincosf(0.5f * p[0],  &s, &c); g_rx<8>(c, s, sr, si);
    __sincosf(0.5f * p[1],  &s, &c); g_ry<8>(c, s, sr, si);
    __sincosf(0.5f * p[2],  &s, &c); g_rz<8>(c, s, sr, si);
    __sincosf(0.5f * p[3],  &s, &c); g_rx<4>(c, s, sr, si);
    __sincosf(0.5f * p[4],  &s, &c); g_ry<4>(c, s, sr, si);
    __sincosf(0.5f * p[5],  &s, &c); g_rz<4>(c, s, sr, si);
    __sincosf(0.5f * p[6],  &s, &c); g_rx<2>(c, s, sr, si);
    __sincosf(0.5f * p[7],  &s, &c); g_ry<2>(c, s, sr, si);
    __sincosf(0.5f * p[8],  &s, &c); g_rz<2>(c, s, sr, si);
    __sincosf(0.5f * p[9],  &s, &c); g_rx<1>(c, s, sr, si);
    __sincosf(0.5f * p[10], &s, &c); g_ry<1>(c, s, sr, si);
    __sincosf(0.5f * p[11], &s, &c); g_rz<1>(c, s, sr, si);
    __sincosf(0.5f * p[12], &s, &c); g_crx<8, 4>(c, s, sr, si);
    __sincosf(0.5f * p[13], &s, &c); g_crx<4, 2>(c, s, sr, si);
    __sincosf(0.5f * p[14], &s, &c); g_crx<2, 1>(c, s, sr, si);
    __sincosf(0.5f * p[15], &s, &c); g_crx<1, 8>(c, s, sr, si);
    __sincosf(0.5f * p[16], &s, &c); g_crx<1, 2>(c, s, sr, si);
    __sincosf(0.5f * p[17], &s, &c); g_crx<2, 4>(c, s, sr, si);
    __sincosf(0.5f * p[18], &s, &c); g_crx<4, 8>(c, s, sr, si);
    __sincosf(0.5f * p[19], &s, &c); g_crx<8, 1>(c, s, sr, si);
}

__global__ __launch_bounds__(THREADS, 3)
void qac_kernel(const float* __restrict__ tsp,      // (B, T, 40)
                const float* __restrict__ poly,     // (4,)
                const float* __restrict__ mix_re,   // (200,)
                const float* __restrict__ mix_im,   // (200,)
                const float* __restrict__ qff,      // (20,)
                float* __restrict__ out)            // (B, 12)
{
    extern __shared__ float sm[];
    float* tab  = sm;                       // [NSLOT][T_STEPS], transposed
    float* wv   = sm + NSLOT * T_STEPS;     // 32
    float* accv = wv + 32;                  // 32
    float* part = accv + 32;                // 8*32

    const int b    = blockIdx.x;
    const int tid  = threadIdx.x;
    const int lane = tid & 31;
    const int warp = tid >> 5;

    // ---- Precompute: per-timestep gate table (built once, reused for 3 k) ----
    if (tid < T_STEPS) {
        const float4* p4 = (const float4*)(tsp + (size_t)b * (T_STEPS * NROTS) + tid * NROTS);
        float pr[NROTS];
#pragma unroll
        for (int j = 0; j < NROTS / 4; j++) {
            float4 v = p4[j];
            pr[4 * j] = v.x; pr[4 * j + 1] = v.y; pr[4 * j + 2] = v.z; pr[4 * j + 3] = v.w;
        }
        float* col = tab + tid;
#pragma unroll
        for (int l = 0; l < 2; l++) {
            const int base = l * 32;
#pragma unroll
            for (int q = 0; q < 4; q++) {
                float ca, sa, cb, sb, cg, sg;
                __sincosf(0.5f * pr[20 * l + 3 * q],     &sa, &ca);
                __sincosf(0.5f * pr[20 * l + 3 * q + 1], &sb, &cb);
                __sincosf(0.5f * pr[20 * l + 3 * q + 2], &sg, &cg);
                float cbca = cb * ca, cbsa = cb * sa, sbca = sb * ca, sbsa = sb * sa;
                float u00r = fmaf(cg, cbca,  sg * sbsa);
                float u00i = fmaf(cg, sbsa, -sg * cbca);
                float u01r = -fmaf(cg, sbca,  sg * cbsa);
                float u01i = fmaf(sg, sbca, -cg * cbsa);
                col[(base + 4 * q    ) * T_STEPS] = u00r;
                col[(base + 4 * q + 1) * T_STEPS] = u00i;
                col[(base + 4 * q + 2) * T_STEPS] = u01r;
                col[(base + 4 * q + 3) * T_STEPS] = u01i;
            }
#pragma unroll
            for (int g = 0; g < 8; g++) {
                float c, s;
                __sincosf(0.5f * pr[20 * l + 12 + g], &s, &c);
                col[(base + 16 + 2 * g    ) * T_STEPS] = c;
                col[(base + 16 + 2 * g + 1) * T_STEPS] = s;
            }
        }
        col[64 * T_STEPS] = mix_re[tid];
        col[65 * T_STEPS] = mix_im[tid];
    }
    if (tid < 32) {
        wv[tid]   = (tid == 0) ? 1.0f : 0.0f;
        accv[tid] = (tid == 0) ? poly[0] : 0.0f;
    }
    __syncthreads();

    const float* col = tab + tid;
    float cr = 0.0f, ci = 0.0f;
    if (tid < T_STEPS) { cr = col[64 * T_STEPS]; ci = col[65 * T_STEPS]; }

    // ---- QSVT iterations ----
#pragma unroll 1
    for (int k = 1; k <= DEG; k++) {
        float a[32];
        if (tid < T_STEPS) {
            u64 vr[8], vi[8];
#pragma unroll
            for (int j = 0; j < 8; j++) {
                vr[j] = pk2(wv[2 * j],      wv[2 * j + 1]);
                vi[j] = pk2(wv[16 + 2 * j], wv[17 + 2 * j]);
            }
#pragma unroll
            for (int l = 0; l < 2; l++) {
                const int base = l * 32;
                su2_pk<4>(col[(base + 0)  * T_STEPS], col[(base + 1)  * T_STEPS],
                          col[(base + 2)  * T_STEPS], col[(base + 3)  * T_STEPS], vr, vi);
                su2_pk<2>(col[(base + 4)  * T_STEPS], col[(base + 5)  * T_STEPS],
                          col[(base + 6)  * T_STEPS], col[(base + 7)  * T_STEPS], vr, vi);
                su2_pk<1>(col[(base + 8)  * T_STEPS], col[(base + 9)  * T_STEPS],
                          col[(base + 10) * T_STEPS], col[(base + 11) * T_STEPS], vr, vi);
                su2_w1  (col[(base + 12) * T_STEPS], col[(base + 13) * T_STEPS],
                         col[(base + 14) * T_STEPS], col[(base + 15) * T_STEPS], vr, vi);
                // CRX ring forward: <8,4>, <4,2>, <2,1>, <1,8>
                crx_pk<4, 2>(col[(base + 16) * T_STEPS], col[(base + 17) * T_STEPS], vr, vi);
                crx_pk<2, 1>(col[(base + 18) * T_STEPS], col[(base + 19) * T_STEPS], vr, vi);
                crx_tw1<1>  (col[(base + 20) * T_STEPS], col[(base + 21) * T_STEPS], vr, vi);
                crx_cw1<4>  (col[(base + 22) * T_STEPS], col[(base + 23) * T_STEPS], vr, vi);
                // CRX ring backward: <1,2>, <2,4>, <4,8>, <8,1>
                crx_cw1<1>  (col[(base + 24) * T_STEPS], col[(base + 25) * T_STEPS], vr, vi);
                crx_pk<1, 2>(col[(base + 26) * T_STEPS], col[(base + 27) * T_STEPS], vr, vi);
                crx_pk<2, 4>(col[(base + 28) * T_STEPS], col[(base + 29) * T_STEPS], vr, vi);
                crx_tw1<4>  (col[(base + 30) * T_STEPS], col[(base + 31) * T_STEPS], vr, vi);
            }
            // multiply by coeff (cr + i*ci), unpack to scalars for reduction
            u64 CR = pk2(cr, cr), CI = pk2(ci, ci), nCI = pk2(-ci, -ci);
#pragma unroll
            for (int j = 0; j < 8; j++) {
                u64 ar = fma2(CR, vr[j], mul2(nCI, vi[j]));
                u64 ai = fma2(CR, vi[j], mul2(CI,  vr[j]));
                upk2(ar, a[2 * j],      a[2 * j + 1]);
                upk2(ai, a[16 + 2 * j], a[17 + 2 * j]);
            }
        } else {
#pragma unroll
            for (int q = 0; q < 32; q++) a[q] = 0.0f;
        }

        // Payload-splitting warp reduction: 31 SHFL total.
#pragma unroll
        for (int m = 16; m >= 1; m >>= 1) {
            const bool hi = (lane & m) != 0;
#pragma unroll
            for (int s = 0; s < m; s++) {
                float snd = hi ? a[s] : a[s + m];
                float kep = hi ? a[s + m] : a[s];
                a[s] = kep + __shfl_xor_sync(0xffffffffu, snd, m);
            }
        }
        part[warp * 32 + lane] = a[0];
        __syncthreads();
        if (tid < 32) {
            float sum = 0.0f;
#pragma unroll
            for (int w = 0; w < THREADS / 32; w++) sum += part[w * 32 + tid];
            wv[tid] = sum;
            accv[tid] = fmaf(poly[k], sum, accv[tid]);
        }
        __syncthreads();
    }

    // ---- Epilogue ----
    if (tid == 0) {
        float l1 = fabsf(poly[0]) + fabsf(poly[1]) + fabsf(poly[2]) + fabsf(poly[3]);
        float inv_l1 = 1.0f / l1;
        float sr[16], si[16];
        float n2 = 0.0f;
#pragma unroll
        for (int q = 0; q < 16; q++) {
            sr[q] = accv[q] * inv_l1;
            si[q] = accv[16 + q] * inv_l1;
            n2 = fmaf(sr[q], sr[q], fmaf(si[q], si[q], n2));
        }
        float inv_n = 1.0f / (sqrtf(n2) + 1e-9f);
#pragma unroll
        for (int q = 0; q < 16; q++) { sr[q] *= inv_n; si[q] *= inv_n; }

        float qp[QFF_NROTS];
#pragma unroll
        for (int j = 0; j < QFF_NROTS; j++) qp[j] = qff[j];
        ansatz_layer_ref(qp, sr, si);

        float* o = out + b * 12;
#pragma unroll
        for (int qi = 0; qi < NQ; qi++) {
            const int W = 8 >> qi;
            float X = 0.0f, Y = 0.0f, Z = 0.0f;
#pragma unroll
            for (int i0 = 0; i0 < DIM; i0++) {
                if (!(i0 & W)) {
                    int j0 = i0 | W;
                    X += 2.0f * (sr[i0] * sr[j0] + si[i0] * si[j0]);
                    Y += 2.0f * (sr[i0] * si[j0] - si[i0] * sr[j0]);
                    Z += (sr[i0] * sr[i0] + si[i0] * si[i0])
                       - (sr[j0] * sr[j0] + si[j0] * si[j0]);
                }
            }
            o[qi] = X; o[4 + qi] = Y; o[8 + qi] = Z;
        }
    }
}

extern "C" void kernel_launch(void* const* d_in, const int* in_sizes, int n_in,
                              void* d_out, int out_size) {
    const float* tsp    = (const float*)d_in[0];
    const float* poly   = (const float*)d_in[1];
    const float* mix_re = (const float*)d_in[2];
    const float* mix_im = (const float*)d_in[3];
    const float* qff    = (const float*)d_in[4];
    float* out = (float*)d_out;
    int B = in_sizes[0] / (T_STEPS * NROTS);   // 2048

    const int smem_bytes = SMEM_FLOATS * sizeof(float);   // ~54KB
    cudaFuncSetAttribute(qac_kernel, cudaFuncAttributeMaxDynamicSharedMemorySize, smem_bytes);
    qac_kernel<<<B, THREADS, smem_bytes>>>(tsp, poly, mix_re, mix_im, qff, out);
}

// round 6
// speedup vs baseline: 1.3713x; 1.0988x over previous
#include <cuda_runtime.h>

// Problem constants
#define NQ 4
#define DIM 16
#define T_STEPS 200
#define NROTS 40      // 5*NQ*NL, NL=2
#define QFF_NROTS 20
#define DEG 3
#define THREADS 256
#define NSLOT 68      // gate-table slots per timestep (coeff folded into gate 0)

#define SMEM_FLOATS (NSLOT * T_STEPS + 32 + 32 + 8 * 32)

typedef unsigned long long u64;

// ---------- packed f32x2 primitives ----------
__device__ __forceinline__ u64 pk2(float lo, float hi) {
    u64 r; asm("mov.b64 %0, {%1, %2};" : "=l"(r) : "f"(lo), "f"(hi)); return r;
}
__device__ __forceinline__ void upk2(u64 v, float& lo, float& hi) {
    asm("mov.b64 {%0, %1}, %2;" : "=f"(lo), "=f"(hi) : "l"(v));
}
__device__ __forceinline__ u64 swap2(u64 v) {
    float lo, hi; upk2(v, lo, hi); return pk2(hi, lo);
}
__device__ __forceinline__ u64 fma2(u64 a, u64 b, u64 c) {
    u64 d; asm("fma.rn.f32x2 %0, %1, %2, %3;" : "=l"(d) : "l"(a), "l"(b), "l"(c)); return d;
}
__device__ __forceinline__ u64 mul2(u64 a, u64 b) {
    u64 d; asm("mul.rn.f32x2 %0, %1, %2;" : "=l"(d) : "l"(a), "l"(b)); return d;
}

// ---------- packed gates on state vr[8], vi[8] (pack j = amplitudes 2j, 2j+1) ----------

// General 2x2 gate (coeff-folded), qubit pack-weight PW (PW in {4,2,1}).
template<int PW>
__device__ __forceinline__ void su2_gen(float g00r, float g00i, float g01r, float g01i,
                                        float g10r, float g10i, float g11r, float g11i,
                                        u64* vr, u64* vi) {
    u64 A  = pk2(g00r, g00r), Ai = pk2(g00i, g00i), nAi = pk2(-g00i, -g00i);
    u64 B  = pk2(g01r, g01r), Bi = pk2(g01i, g01i), nBi = pk2(-g01i, -g01i);
    u64 C  = pk2(g10r, g10r), Ci = pk2(g10i, g10i), nCi = pk2(-g10i, -g10i);
    u64 D  = pk2(g11r, g11r), Di = pk2(g11i, g11i), nDi = pk2(-g11i, -g11i);
#pragma unroll
    for (int j = 0; j < 8; j++) {
        if (!(j & PW)) {
            const int q = j | PW;
            u64 r0 = vr[j], i0 = vi[j], r1 = vr[q], i1 = vi[q];
            vr[j] = fma2(A, r0, fma2(nAi, i0, fma2(B, r1, mul2(nBi, i1))));
            vi[j] = fma2(A, i0, fma2(Ai,  r0, fma2(B, i1, mul2(Bi,  r1))));
            vr[q] = fma2(C, r0, fma2(nCi, i0, fma2(D, r1, mul2(nDi, i1))));
            vi[q] = fma2(C, i0, fma2(Ci,  r0, fma2(D, i1, mul2(Di,  r1))));
        }
    }
}

// Fused SU(2), qubit pack-weight PW (PW in {4,2,1}).
template<int PW>
__device__ __forceinline__ void su2_pk(float u00r, float u00i, float u01r, float u01i,
                                       u64* vr, u64* vi) {
    u64 A   = pk2(u00r, u00r),  Ai  = pk2(u00i, u00i),  nAi = pk2(-u00i, -u00i);
    u64 B   = pk2(u01r, u01r),  nB  = pk2(-u01r, -u01r);
    u64 Bi  = pk2(u01i, u01i),  nBi = pk2(-u01i, -u01i);
#pragma unroll
    for (int j = 0; j < 8; j++) {
        if (!(j & PW)) {
            const int q = j | PW;
            u64 r0 = vr[j], i0 = vi[j], r1 = vr[q], i1 = vi[q];
            vr[j] = fma2(A, r0, fma2(nAi, i0, fma2(B,  r1, mul2(nBi, i1))));
            vi[j] = fma2(A, i0, fma2(Ai,  r0, fma2(B,  i1, mul2(Bi,  r1))));
            vr[q] = fma2(A, r1, fma2(Ai,  i1, fma2(nB, r0, mul2(nBi, i0))));
            vi[q] = fma2(A, i1, fma2(nAi, r1, fma2(nB, i0, mul2(Bi,  r0))));
        }
    }
}

// Fused SU(2), qubit weight 1 (partner inside pack; swapped-operand form).
__device__ __forceinline__ void su2_w1(float u00r, float u00i, float u01r, float u01i,
                                       u64* vr, u64* vi) {
    u64 P  = pk2(u00r,  u00r);
    u64 Q  = pk2(u01r, -u01r);
    u64 R  = pk2(-u00i, u00i);
    u64 S  = pk2(-u01i, -u01i);
    u64 R2 = pk2(u00i, -u00i);
    u64 S2 = pk2(u01i,  u01i);
#pragma unroll
    for (int j = 0; j < 8; j++) {
        u64 rp = vr[j], ip = vi[j];
        u64 rs = swap2(rp), is = swap2(ip);
        vr[j] = fma2(P, rp, fma2(Q, rs, fma2(R,  ip, mul2(S,  is))));
        vi[j] = fma2(P, ip, fma2(Q, is, fma2(R2, rp, mul2(S2, rs))));
    }
}

// CRX, control pack-weight PCW (>=1 pack bit), target pack-weight PPW (>=1).
template<int PCW, int PPW>
__device__ __forceinline__ void crx_pk(float c, float s, u64* vr, u64* vi) {
    u64 C = pk2(c, c), Sp = pk2(s, s), nS = pk2(-s, -s);
#pragma unroll
    for (int j = 0; j < 8; j++) {
        if ((j & PCW) && !(j & PPW)) {
            const int q = j | PPW;
            u64 r0 = vr[j], i0 = vi[j], r1 = vr[q], i1 = vi[q];
            vr[j] = fma2(C, r0, mul2(Sp, i1));
            vi[j] = fma2(C, i0, mul2(nS, r1));
            vr[q] = fma2(C, r1, mul2(Sp, i0));
            vi[q] = fma2(C, i1, mul2(nS, r0));
        }
    }
}

// CRX with control weight 1 (control bit = half index): masked coeffs.
template<int PPW>
__device__ __forceinline__ void crx_cw1(float c, float s, u64* vr, u64* vi) {
    u64 C = pk2(1.0f, c), Sp = pk2(0.0f, s), nS = pk2(0.0f, -s);
#pragma unroll
    for (int j = 0; j < 8; j++) {
        if (!(j & PPW)) {
            const int q = j | PPW;
            u64 r0 = vr[j], i0 = vi[j], r1 = vr[q], i1 = vi[q];
            vr[j] = fma2(C, r0, mul2(Sp, i1));
            vi[j] = fma2(C, i0, mul2(nS, r1));
            vr[q] = fma2(C, r1, mul2(Sp, i0));
            vi[q] = fma2(C, i1, mul2(nS, r0));
        }
    }
}

// CRX with target weight 1 (pair inside pack), control pack-weight PCW.
template<int PCW>
__device__ __forceinline__ void crx_tw1(float c, float s, u64* vr, u64* vi) {
    u64 C = pk2(c, c), Sp = pk2(s, s), nS = pk2(-s, -s);
#pragma unroll
    for (int j = 0; j < 8; j++) {
        if (j & PCW) {
            u64 rs = swap2(vr[j]), is = swap2(vi[j]);
            vr[j] = fma2(C, vr[j], mul2(Sp, is));
            vi[j] = fma2(C, vi[j], mul2(nS, rs));
        }
    }
}

// ---------- fused single-qubit SU(2) from 3 angles (precompute) ----------
__device__ __forceinline__ void fuse_su2(float pa, float pb, float pg,
                                         float& u00r, float& u00i,
                                         float& u01r, float& u01i) {
    float ca, sa, cb, sb, cg, sg;
    __sincosf(0.5f * pa, &sa, &ca);
    __sincosf(0.5f * pb, &sb, &cb);
    __sincosf(0.5f * pg, &sg, &cg);
    float cbca = cb * ca, cbsa = cb * sa, sbca = sb * ca, sbsa = sb * sa;
    u00r = fmaf(cg, cbca,  sg * sbsa);
    u00i = fmaf(cg, sbsa, -sg * cbca);
    u01r = -fmaf(cg, sbca,  sg * cbsa);
    u01i = fmaf(sg, sbca, -cg * cbsa);
}

// ---------- scalar rotations (epilogue only) ----------
__device__ __forceinline__ void rot_rx(float c, float s,
                                       float& r0, float& i0, float& r1, float& i1) {
    float nr0 = fmaf(c, r0,  s * i1);
    float ni0 = fmaf(c, i0, -s * r1);
    float nr1 = fmaf(c, r1,  s * i0);
    float ni1 = fmaf(c, i1, -s * r0);
    r0 = nr0; i0 = ni0; r1 = nr1; i1 = ni1;
}
__device__ __forceinline__ void rot_ry(float c, float s,
                                       float& r0, float& i0, float& r1, float& i1) {
    float nr0 = fmaf(c, r0, -s * r1);
    float ni0 = fmaf(c, i0, -s * i1);
    float nr1 = fmaf(c, r1,  s * r0);
    float ni1 = fmaf(c, i1,  s * i0);
    r0 = nr0; i0 = ni0; r1 = nr1; i1 = ni1;
}
__device__ __forceinline__ void rot_rz(float c, float s,
                                       float& r0, float& i0, float& r1, float& i1) {
    float nr0 = fmaf(c, r0,  s * i0);
    float ni0 = fmaf(c, i0, -s * r0);
    float nr1 = fmaf(c, r1, -s * i1);
    float ni1 = fmaf(c, i1,  s * r1);
    r0 = nr0; i0 = ni0; r1 = nr1; i1 = ni1;
}
template<int W>
__device__ __forceinline__ void g_rx(float c, float s, float* sr, float* si) {
#pragma unroll
    for (int i = 0; i < DIM; i++)
        if (!(i & W)) rot_rx(c, s, sr[i], si[i], sr[i | W], si[i | W]);
}
template<int W>
__device__ __forceinline__ void g_ry(float c, float s, float* sr, float* si) {
#pragma unroll
    for (int i = 0; i < DIM; i++)
        if (!(i & W)) rot_ry(c, s, sr[i], si[i], sr[i | W], si[i | W]);
}
template<int W>
__device__ __forceinline__ void g_rz(float c, float s, float* sr, float* si) {
#pragma unroll
    for (int i = 0; i < DIM; i++)
        if (!(i & W)) rot_rz(c, s, sr[i], si[i], sr[i | W], si[i | W]);
}
template<int CW, int TW>
__device__ __forceinline__ void g_crx(float c, float s, float* sr, float* si) {
#pragma unroll
    for (int i = 0; i < DIM; i++)
        if ((i & CW) && !(i & TW)) rot_rx(c, s, sr[i], si[i], sr[i | TW], si[i | TW]);
}
__device__ __forceinline__ void ansatz_layer_ref(const float* p, float* sr, float* si) {
    float c, s;
    __sincosf(0.5f * p[0],  &s, &c); g_rx<8>(c, s, sr, si);
    __sincosf(0.5f * p[1],  &s, &c); g_ry<8>(c, s, sr, si);
    __sincosf(0.5f * p[2],  &s, &c); g_rz<8>(c, s, sr, si);
    __sincosf(0.5f * p[3],  &s, &c); g_rx<4>(c, s, sr, si);
    __sincosf(0.5f * p[4],  &s, &c); g_ry<4>(c, s, sr, si);
    __sincosf(0.5f * p[5],  &s, &c); g_rz<4>(c, s, sr, si);
    __sincosf(0.5f * p[6],  &s, &c); g_rx<2>(c, s, sr, si);
    __sincosf(0.5f * p[7],  &s, &c); g_ry<2>(c, s, sr, si);
    __sincosf(0.5f * p[8],  &s, &c); g_rz<2>(c, s, sr, si);
    __sincosf(0.5f * p[9],  &s, &c); g_rx<1>(c, s, sr, si);
    __sincosf(0.5f * p[10], &s, &c); g_ry<1>(c, s, sr, si);
    __sincosf(0.5f * p[11], &s, &c); g_rz<1>(c, s, sr, si);
    __sincosf(0.5f * p[12], &s, &c); g_crx<8, 4>(c, s, sr, si);
    __sincosf(0.5f * p[13], &s, &c); g_crx<4, 2>(c, s, sr, si);
    __sincosf(0.5f * p[14], &s, &c); g_crx<2, 1>(c, s, sr, si);
    __sincosf(0.5f * p[15], &s, &c); g_crx<1, 8>(c, s, sr, si);
    __sincosf(0.5f * p[16], &s, &c); g_crx<1, 2>(c, s, sr, si);
    __sincosf(0.5f * p[17], &s, &c); g_crx<2, 4>(c, s, sr, si);
    __sincosf(0.5f * p[18], &s, &c); g_crx<4, 8>(c, s, sr, si);
    __sincosf(0.5f * p[19], &s, &c); g_crx<8, 1>(c, s, sr, si);
}

__global__ __launch_bounds__(THREADS, 4)
void qac_kernel(const float* __restrict__ tsp,      // (B, T, 40)
                const float* __restrict__ poly,     // (4,)
                const float* __restrict__ mix_re,   // (200,)
                const float* __restrict__ mix_im,   // (200,)
                const float* __restrict__ qff,      // (20,)
                float* __restrict__ out)            // (B, 12)
{
    extern __shared__ float sm[];
    float* tab  = sm;                       // [NSLOT][T_STEPS], transposed
    float* wv   = sm + NSLOT * T_STEPS;     // 32 (8B-aligned)
    float* accv = wv + 32;                  // 32
    float* part = accv + 32;                // 8*32

    const int b    = blockIdx.x;
    const int tid  = threadIdx.x;
    const int lane = tid & 31;
    const int warp = tid >> 5;

    // ---- Precompute: per-timestep gate table (built once, reused for 3 k) ----
    if (tid < T_STEPS) {
        const float4* p4 = (const float4*)(tsp + (size_t)b * (T_STEPS * NROTS) + tid * NROTS);
        float* col = tab + tid;
        const float cr = mix_re[tid], ci = mix_im[tid];

        // layer 0 single-qubit fused gates (float4 streamed, no big array)
        float4 v0 = p4[0], v1 = p4[1], v2 = p4[2];
        {
            float u00r, u00i, u01r, u01i;
            fuse_su2(v0.x, v0.y, v0.z, u00r, u00i, u01r, u01i);
            // coeff-folded general 2x2: G = (cr + i*ci) * U
            col[0 * T_STEPS] = cr * u00r - ci * u00i;           // G00r
            col[1 * T_STEPS] = cr * u00i + ci * u00r;           // G00i
            col[2 * T_STEPS] = cr * u01r - ci * u01i;           // G01r
            col[3 * T_STEPS] = cr * u01i + ci * u01r;           // G01i
            col[4 * T_STEPS] = -(cr * u01r + ci * u01i);        // G10r = c*(-conj u01) re
            col[5 * T_STEPS] = cr * u01i - ci * u01r;           // G10i
            col[6 * T_STEPS] = cr * u00r + ci * u00i;           // G11r = c*conj(u00) re
            col[7 * T_STEPS] = ci * u00r - cr * u00i;           // G11i
        }
        {
            float a, bq, g, d;
            fuse_su2(v0.w, v1.x, v1.y, a, bq, g, d);
            col[8  * T_STEPS] = a;  col[9  * T_STEPS] = bq;
            col[10 * T_STEPS] = g;  col[11 * T_STEPS] = d;
            fuse_su2(v1.z, v1.w, v2.x, a, bq, g, d);
            col[12 * T_STEPS] = a;  col[13 * T_STEPS] = bq;
            col[14 * T_STEPS] = g;  col[15 * T_STEPS] = d;
            fuse_su2(v2.y, v2.z, v2.w, a, bq, g, d);
            col[16 * T_STEPS] = a;  col[17 * T_STEPS] = bq;
            col[18 * T_STEPS] = g;  col[19 * T_STEPS] = d;
        }
        // layer 0 CRX gates
        {
            float4 c0 = p4[3], c1 = p4[4];
            float ang[8] = {c0.x, c0.y, c0.z, c0.w, c1.x, c1.y, c1.z, c1.w};
#pragma unroll
            for (int g = 0; g < 8; g++) {
                float c, s;
                __sincosf(0.5f * ang[g], &s, &c);
                col[(20 + 2 * g) * T_STEPS] = c;
                col[(21 + 2 * g) * T_STEPS] = s;
            }
        }
        // layer 1
        float4 v3 = p4[5], v4 = p4[6], v5 = p4[7];
        {
            float a, bq, g, d;
            fuse_su2(v3.x, v3.y, v3.z, a, bq, g, d);
            col[36 * T_STEPS] = a;  col[37 * T_STEPS] = bq;
            col[38 * T_STEPS] = g;  col[39 * T_STEPS] = d;
            fuse_su2(v3.w, v4.x, v4.y, a, bq, g, d);
            col[40 * T_STEPS] = a;  col[41 * T_STEPS] = bq;
            col[42 * T_STEPS] = g;  col[43 * T_STEPS] = d;
            fuse_su2(v4.z, v4.w, v5.x, a, bq, g, d);
            col[44 * T_STEPS] = a;  col[45 * T_STEPS] = bq;
            col[46 * T_STEPS] = g;  col[47 * T_STEPS] = d;
            fuse_su2(v5.y, v5.z, v5.w, a, bq, g, d);
            col[48 * T_STEPS] = a;  col[49 * T_STEPS] = bq;
            col[50 * T_STEPS] = g;  col[51 * T_STEPS] = d;
        }
        {
            float4 c2 = p4[8], c3 = p4[9];
            float ang[8] = {c2.x, c2.y, c2.z, c2.w, c3.x, c3.y, c3.z, c3.w};
#pragma unroll
            for (int g = 0; g < 8; g++) {
                float c, s;
                __sincosf(0.5f * ang[g], &s, &c);
                col[(52 + 2 * g) * T_STEPS] = c;
                col[(53 + 2 * g) * T_STEPS] = s;
            }
        }
    }
    if (tid < 32) {
        wv[tid]   = (tid == 0) ? 1.0f : 0.0f;
        accv[tid] = (tid == 0) ? poly[0] : 0.0f;
    }
    __syncthreads();

    const float* col = tab + tid;

    // ---- QSVT iterations: work_k = sum_t (c_t U_t) work_{k-1} (coeff in table) ----
#pragma unroll 1
    for (int k = 1; k <= DEG; k++) {
        float a[32];
        if (tid < T_STEPS) {
            u64 vr[8], vi[8];
            const u64* wv64 = (const u64*)wv;
#pragma unroll
            for (int j = 0; j < 8; j++) { vr[j] = wv64[j]; vi[j] = wv64[8 + j]; }

            // layer 0 (gate 0 carries the LCU coefficient)
            su2_gen<4>(col[0 * T_STEPS], col[1 * T_STEPS], col[2 * T_STEPS], col[3 * T_STEPS],
                       col[4 * T_STEPS], col[5 * T_STEPS], col[6 * T_STEPS], col[7 * T_STEPS],
                       vr, vi);
            su2_pk<2>(col[8  * T_STEPS], col[9  * T_STEPS],
                      col[10 * T_STEPS], col[11 * T_STEPS], vr, vi);
            su2_pk<1>(col[12 * T_STEPS], col[13 * T_STEPS],
                      col[14 * T_STEPS], col[15 * T_STEPS], vr, vi);
            su2_w1  (col[16 * T_STEPS], col[17 * T_STEPS],
                     col[18 * T_STEPS], col[19 * T_STEPS], vr, vi);
            crx_pk<4, 2>(col[20 * T_STEPS], col[21 * T_STEPS], vr, vi);  // <8,4>
            crx_pk<2, 1>(col[22 * T_STEPS], col[23 * T_STEPS], vr, vi);  // <4,2>
            crx_tw1<1>  (col[24 * T_STEPS], col[25 * T_STEPS], vr, vi);  // <2,1>
            crx_cw1<4>  (col[26 * T_STEPS], col[27 * T_STEPS], vr, vi);  // <1,8>
            crx_cw1<1>  (col[28 * T_STEPS], col[29 * T_STEPS], vr, vi);  // <1,2>
            crx_pk<1, 2>(col[30 * T_STEPS], col[31 * T_STEPS], vr, vi);  // <2,4>
            crx_pk<2, 4>(col[32 * T_STEPS], col[33 * T_STEPS], vr, vi);  // <4,8>
            crx_tw1<4>  (col[34 * T_STEPS], col[35 * T_STEPS], vr, vi);  // <8,1>

            // layer 1
            su2_pk<4>(col[36 * T_STEPS], col[37 * T_STEPS],
                      col[38 * T_STEPS], col[39 * T_STEPS], vr, vi);
            su2_pk<2>(col[40 * T_STEPS], col[41 * T_STEPS],
                      col[42 * T_STEPS], col[43 * T_STEPS], vr, vi);
            su2_pk<1>(col[44 * T_STEPS], col[45 * T_STEPS],
                      col[46 * T_STEPS], col[47 * T_STEPS], vr, vi);
            su2_w1  (col[48 * T_STEPS], col[49 * T_STEPS],
                     col[50 * T_STEPS], col[51 * T_STEPS], vr, vi);
            crx_pk<4, 2>(col[52 * T_STEPS], col[53 * T_STEPS], vr, vi);
            crx_pk<2, 1>(col[54 * T_STEPS], col[55 * T_STEPS], vr, vi);
            crx_tw1<1>  (col[56 * T_STEPS], col[57 * T_STEPS], vr, vi);
            crx_cw1<4>  (col[58 * T_STEPS], col[59 * T_STEPS], vr, vi);
            crx_cw1<1>  (col[60 * T_STEPS], col[61 * T_STEPS], vr, vi);
            crx_pk<1, 2>(col[62 * T_STEPS], col[63 * T_STEPS], vr, vi);
            crx_pk<2, 4>(col[64 * T_STEPS], col[65 * T_STEPS], vr, vi);
            crx_tw1<4>  (col[66 * T_STEPS], col[67 * T_STEPS], vr, vi);

#pragma unroll
            for (int j = 0; j < 8; j++) {
                upk2(vr[j], a[2 * j],      a[2 * j + 1]);
                upk2(vi[j], a[16 + 2 * j], a[17 + 2 * j]);
            }
        } else {
#pragma unroll
            for (int q = 0; q < 32; q++) a[q] = 0.0f;
        }

        // Payload-splitting warp reduction: 31 SHFL total.
#pragma unroll
        for (int m = 16; m >= 1; m >>= 1) {
            const bool hi = (lane & m) != 0;
#pragma unroll
            for (int s = 0; s < m; s++) {
                float snd = hi ? a[s] : a[s + m];
                float kep = hi ? a[s + m] : a[s];
                a[s] = kep + __shfl_xor_sync(0xffffffffu, snd, m);
            }
        }
        part[warp * 32 + lane] = a[0];
        __syncthreads();
        if (tid < 32) {
            float sum = 0.0f;
#pragma unroll
            for (int w = 0; w < THREADS / 32; w++) sum += part[w * 32 + tid];
            wv[tid] = sum;
            accv[tid] = fmaf(poly[k], sum, accv[tid]);
        }
        __syncthreads();
    }

    // ---- Epilogue ----
    if (tid == 0) {
        float l1 = fabsf(poly[0]) + fabsf(poly[1]) + fabsf(poly[2]) + fabsf(poly[3]);
        float inv_l1 = 1.0f / l1;
        float sr[16], si[16];
        float n2 = 0.0f;
#pragma unroll
        for (int q = 0; q < 16; q++) {
            sr[q] = accv[q] * inv_l1;
            si[q] = accv[16 + q] * inv_l1;
            n2 = fmaf(sr[q], sr[q], fmaf(si[q], si[q], n2));
        }
        float inv_n = 1.0f / (sqrtf(n2) + 1e-9f);
#pragma unroll
        for (int q = 0; q < 16; q++) { sr[q] *= inv_n; si[q] *= inv_n; }

        float qp[QFF_NROTS];
#pragma unroll
        for (int j = 0; j < QFF_NROTS; j++) qp[j] = qff[j];
        ansatz_layer_ref(qp, sr, si);

        float* o = out + b * 12;
#pragma unroll
        for (int qi = 0; qi < NQ; qi++) {
            const int W = 8 >> qi;
            float X = 0.0f, Y = 0.0f, Z = 0.0f;
#pragma unroll
            for (int i0 = 0; i0 < DIM; i0++) {
                if (!(i0 & W)) {
                    int j0 = i0 | W;
                    X += 2.0f * (sr[i0] * sr[j0] + si[i0] * si[j0]);
                    Y += 2.0f * (sr[i0] * si[j0] - si[i0] * sr[j0]);
                    Z += (sr[i0] * sr[i0] + si[i0] * si[i0])
                       - (sr[j0] * sr[j0] + si[j0] * si[j0]);
                }
            }
            o[qi] = X; o[4 + qi] = Y; o[8 + qi] = Z;
        }
    }
}

extern "C" void kernel_launch(void* const* d_in, const int* in_sizes, int n_in,
                              void* d_out, int out_size) {
    const float* tsp    = (const float*)d_in[0];
    const float* poly   = (const float*)d_in[1];
    const float* mix_re = (const float*)d_in[2];
    const float* mix_im = (const float*)d_in[3];
    const float* qff    = (const float*)d_in[4];
    float* out = (float*)d_out;
    int B = in_sizes[0] / (T_STEPS * NROTS);   // 2048

    const int smem_bytes = SMEM_FLOATS * sizeof(float);   // ~55.7KB
    cudaFuncSetAttribute(qac_kernel, cudaFuncAttributeMaxDynamicSharedMemorySize, smem_bytes);
    qac_kernel<<<B, THREADS, smem_bytes>>>(tsp, poly, mix_re, mix_im, qff, out);
}